// round 15
// baseline (speedup 1.0000x reference)
#include <cuda_runtime.h>
#include <cuda_bf16.h>

// 3x3 stride-2 VALID average pooling, fp32.
// x: (8, 64, 512, 512) -> out: (8, 64, 255, 255)
//
// Barrier-free register-rolling, half-width CTAs (finer granularity to cut
// end-of-kernel drain). 64 threads per CTA; thread t owns output cols
// (128h + 2t, 128h + 2t + 1) <- input cols 256h + 4t .. 4t+4:
// one coalesced float4 load per row + one L1-hot scalar for the overlap
// element. Vertical 3-row overlap carried in registers (read-once).

#define IN_H 512
#define IN_W 512
#define OUT_H 255
#define OUT_W 255
#define RPB 15          // output rows per strip (255 = 15 * 17, exact)
#define STRIPS 17
#define NT 64           // 64 threads x 2 output cols = 128-col half-band

__global__ __launch_bounds__(NT)
void KeyedAvgpool2d_2413771620972_kernel(const float* __restrict__ x,
                                         float* __restrict__ out)
{
    const int rb = blockIdx.x;    // strip (fastest axis: boundary-row L2 reuse)
    const int h  = blockIdx.y;    // width half (0 or 1)
    const int nc = blockIdx.z;    // plane (N*C)
    const int t  = threadIdx.x;

    const float* __restrict__ plane = x + (size_t)nc * IN_H * IN_W;
    // float4 lane pointer: column block 64h + t within each 128-float4 row
    const float4* __restrict__ p4 =
        reinterpret_cast<const float4*>(plane) + 64 * h + t;

    const int  ecol = 256 * h + 4 * t + 4;   // overlap element column
    const bool full = (ecol < IN_W);         // false only for h=1, t=63
                                             // (also exactly when ow1==255 invalid)
    const int  oh0  = rb * RPB;
    const float inv9 = 1.0f / 9.0f;

    // Carried horizontal pair-sums of input row 2*oh0 (shared top row).
    float a_c, b_c;
    {
        const int ih = 2 * oh0;
        float4 v = p4[(size_t)ih * (IN_W / 4)];
        float  e = full ? plane[(size_t)ih * IN_W + ecol] : 0.0f;
        a_c = v.x + v.y + v.z;        // -> output col 128h + 2t
        b_c = v.z + v.w + e;          // -> output col 128h + 2t + 1
    }

    float* __restrict__ op =
        out + (size_t)nc * OUT_H * OUT_W + (size_t)oh0 * OUT_W + 128 * h + 2 * t;

    #pragma unroll
    for (int r = 0; r < RPB; r++) {
        const int ih1 = 2 * (oh0 + r) + 1;

        // Two fresh input rows per output row (read-once property).
        float4 v1 = p4[(size_t)ih1 * (IN_W / 4)];
        float4 v2 = p4[(size_t)(ih1 + 1) * (IN_W / 4)];
        float  e1 = full ? plane[(size_t)ih1 * IN_W + ecol] : 0.0f;
        float  e2 = full ? plane[(size_t)(ih1 + 1) * IN_W + ecol] : 0.0f;

        const float a1 = v1.x + v1.y + v1.z, b1 = v1.z + v1.w + e1;
        const float a2 = v2.x + v2.y + v2.z, b2 = v2.z + v2.w + e2;

        op[0] = (a_c + a1 + a2) * inv9;
        if (full) op[1] = (b_c + b1 + b2) * inv9;

        a_c = a2;                     // bottom row becomes next top row
        b_c = b2;
        op += OUT_W;
    }
}

extern "C" void kernel_launch(void* const* d_in, const int* in_sizes, int n_in,
                              void* d_out, int out_size)
{
    const float* x = (const float*)d_in[0];
    float* out = (float*)d_out;

    dim3 grid(STRIPS, 2, in_sizes[0] / (IN_H * IN_W));   // 17 x 2 x 512
    KeyedAvgpool2d_2413771620972_kernel<<<grid, NT>>>(x, out);
}

// round 16
// speedup vs baseline: 1.0418x; 1.0418x over previous
#include <cuda_runtime.h>
#include <cuda_bf16.h>

// 3x3 stride-2 VALID average pooling, fp32.
// x: (8, 64, 512, 512) -> out: (8, 64, 255, 255)
//
// Register-rolling, barrier-free (R14 shape) + DRAM-efficiency tuning:
//  - st.global.cs (evict-first) output stores: output is never re-read;
//    avoid L2 write-allocate pollution of the read stream.
//  - relaxed register budget so ptxas front-batches more LDG.128s
//    (longer read bursts, fewer DRAM read/write turnarounds).
// Traffic is already optimal (measured 666 MB vs 670 MB ideal).

#define IN_H 512
#define IN_W 512
#define OUT_H 255
#define OUT_W 255
#define RPB 15          // output rows per CTA (255 = 15 * 17, exact)
#define STRIPS 17
#define NT 128          // 128 threads x 2 cols = 256 >= 255 cols

__device__ __forceinline__ void stcs(float* p, float v) {
    asm volatile("st.global.cs.f32 [%0], %1;" :: "l"(p), "f"(v) : "memory");
}

__global__ __launch_bounds__(NT, 8)   // allow up to 64 regs; occupancy proven non-binding
void KeyedAvgpool2d_2413771620972_kernel(const float* __restrict__ x,
                                         float* __restrict__ out)
{
    const int rb = blockIdx.x;    // strip within plane (fast axis: boundary-row L2 reuse)
    const int nc = blockIdx.y;    // plane (N*C)
    const int t  = threadIdx.x;

    const float*  __restrict__ plane = x + (size_t)nc * IN_H * IN_W;
    const float4* __restrict__ p4    = reinterpret_cast<const float4*>(plane);

    const bool full = (t < NT - 1);   // t==127: ow1=255 invalid, elem 4t+4=512 OOB
    const int  oh0  = rb * RPB;
    const float inv9 = 1.0f / 9.0f;

    // Carried horizontal pair-sums of input row 2*oh0 (shared top row).
    float a_c, b_c;
    {
        const int ih = 2 * oh0;
        float4 v = p4[(size_t)ih * (IN_W / 4) + t];
        float  e = full ? plane[(size_t)ih * IN_W + 4 * t + 4] : 0.0f;
        a_c = v.x + v.y + v.z;        // cols 4t..4t+2  -> output 2t
        b_c = v.z + v.w + e;          // cols 4t+2..4t+4 -> output 2t+1
    }

    float* __restrict__ op =
        out + (size_t)nc * OUT_H * OUT_W + (size_t)oh0 * OUT_W + 2 * t;

    #pragma unroll
    for (int r = 0; r < RPB; r++) {
        const int ih1 = 2 * (oh0 + r) + 1;

        // Two fresh input rows per output row (read-once property).
        float4 v1 = p4[(size_t)ih1 * (IN_W / 4) + t];
        float4 v2 = p4[(size_t)(ih1 + 1) * (IN_W / 4) + t];
        float  e1 = full ? plane[(size_t)ih1 * IN_W + 4 * t + 4] : 0.0f;
        float  e2 = full ? plane[(size_t)(ih1 + 1) * IN_W + 4 * t + 4] : 0.0f;

        const float a1 = v1.x + v1.y + v1.z, b1 = v1.z + v1.w + e1;
        const float a2 = v2.x + v2.y + v2.z, b2 = v2.z + v2.w + e2;

        stcs(op, (a_c + a1 + a2) * inv9);
        if (full) stcs(op + 1, (b_c + b1 + b2) * inv9);

        a_c = a2;                     // bottom row becomes next top row
        b_c = b2;
        op += OUT_W;
    }
}

extern "C" void kernel_launch(void* const* d_in, const int* in_sizes, int n_in,
                              void* d_out, int out_size)
{
    const float* x = (const float*)d_in[0];
    float* out = (float*)d_out;

    dim3 grid(STRIPS, in_sizes[0] / (IN_H * IN_W));   // 17 x 512
    KeyedAvgpool2d_2413771620972_kernel<<<grid, NT>>>(x, out);
}